// round 9
// baseline (speedup 1.0000x reference)
#include <cuda_runtime.h>

// Problem constants (fixed shapes for this problem instance)
#define NBOX    2048
#define NBATCH  16
#define AH      256
#define AW      256
#define NBANDS  8          // kernel A: row bands of 32 rows
#define GRID_A  (NBATCH * NBANDS)   // 128
#define GRID_B  1024       // kernel B: 4 rows per block

// Persistent scratch (rewritten fully every replay; no zeroing needed)
__device__ unsigned g_mask[NBATCH * AH * 8];   // 16 x 256 rows x 256 bits = 128 KB
__device__ int      g_has[NBATCH];
__device__ float    g_partial[GRID_B];
__device__ unsigned g_count = 0;

// bce = max(l,0) - l*m + log1p(exp(-|l|)); softplus arg in (1,2] -> fast math safe
__device__ __forceinline__ float bce_elem(float l, unsigned mb) {
    float t  = __expf(-fabsf(l));
    float sp = __logf(1.0f + t);
    float z  = fmaxf(l, 0.0f) - (mb ? l : 0.0f);
    return z + sp;
}

// ---------------- Kernel A: per-(batch, band) union-mask rasterizer ----------
__global__ __launch_bounds__(256, 8)
void raster_kernel(const float* __restrict__ tgt)
{
    const int tid   = threadIdx.x;
    const int batch = blockIdx.x >> 3;       // 0..15
    const int band  = blockIdx.x & 7;        // 0..7
    const int blo   = band << 5;             // first row of band (32 rows)

    __shared__ unsigned s_mask[32 * 8];      // 32 rows x 256 bits
    __shared__ int      s_has;

    s_mask[tid & 255] = 0u;                  // 256 words, one per thread
    if (tid == 0) s_has = 0;
    __syncthreads();

    const float fb = (float)batch;
    int has = 0;

    #pragma unroll
    for (int k = 0; k < NBOX / 256; k++) {
        const float* t = tgt + (size_t)(tid + (k << 8)) * 6;
        if (t[0] == fb) {
            has = 1;
            float xc = t[2], yc = t[3], bw = t[4], bh = t[5];
            float x1 = 1024.0f * (xc - bw * 0.5f);
            float y1 = 1024.0f * (yc - bh * 0.5f);
            float x2 = 1024.0f * (xc + bw * 0.5f);
            float y2 = 1024.0f * (yc + bh * 0.5f);
            bool valid = (x1 <= 1024.0f) && (y1 <= 1024.0f) &&
                         (x2 <= 1024.0f) && (y2 <= 1024.0f);
            int X1 = max(0, (int)truncf(x1 * 0.25f));
            int Y1 = max(0, (int)truncf(y1 * 0.25f));
            int X2 = max(0, min(AW, (int)(ceilf(x2 * 0.25f) + 1.0f)));
            int Y2 = max(0, min(AH, (int)(ceilf(y2 * 0.25f) + 1.0f)));
            int y0 = max(Y1, blo);
            int y1i = min(Y2, blo + 32);
            if (valid && X2 > X1 && y0 < y1i) {
                int w0 = X1 >> 5;
                int w1 = (X2 - 1) >> 5;
                for (int w = w0; w <= w1; w++) {
                    int lo = X1 - (w << 5); lo = (lo < 0) ? 0 : lo;   // 0..31
                    int hi = X2 - (w << 5);                            // >=1
                    unsigned mh  = (hi >= 32) ? 0xFFFFFFFFu : ((1u << hi) - 1u);
                    unsigned msk = mh & ~((1u << lo) - 1u);
                    for (int y = y0; y < y1i; y++)
                        atomicOr(&s_mask[((y - blo) << 3) + w], msk);
                }
            }
        }
    }
    if (has) atomicOr((unsigned*)&s_has, 1u);
    __syncthreads();

    // Store band mask (full overwrite every replay)
    g_mask[(batch << 11) + (band << 8) + tid] = s_mask[tid];
    if (band == 0 && tid == 0) g_has[batch] = s_has;
}

// ---------------- Kernel B: streaming BCE + deterministic reduction ----------
__global__ __launch_bounds__(256, 8)
void bce_kernel(const float* __restrict__ am, float* __restrict__ out)
{
    const int tid   = threadIdx.x;
    const int blk   = blockIdx.x;
    const int batch = blk >> 6;              // 0..15 (64 blocks per batch)

    __shared__ float    s_warp[8];
    __shared__ unsigned s_last;

    // This block's 1024 logits = 4 rows x 256 cols; thread -> one float4
    const float4 v = ((const float4*)am)[(size_t)blk * 256 + tid];

    // Mask bits: row within batch, word, shift
    const int row  = ((blk & 63) << 2) + (tid >> 6);   // 64 float4 per row
    const int col  = (tid & 63) << 2;                  // starting bit
    const unsigned bits =
        g_mask[(batch << 11) + (row << 3) + (col >> 5)] >> (col & 31);

    float sum = bce_elem(v.x,  bits       & 1u)
              + bce_elem(v.y, (bits >> 1) & 1u)
              + bce_elem(v.z, (bits >> 2) & 1u)
              + bce_elem(v.w, (bits >> 3) & 1u);

    #pragma unroll
    for (int off = 16; off; off >>= 1)
        sum += __shfl_down_sync(0xFFFFFFFFu, sum, off);
    if ((tid & 31) == 0) s_warp[tid >> 5] = sum;
    __syncthreads();

    if (tid == 0) {
        float tot = 0.0f;
        #pragma unroll
        for (int w = 0; w < 8; w++) tot += s_warp[w];          // fixed order
        g_partial[blk] = g_has[batch] ? tot * (1.0f / 65536.0f) : 0.0f;
        __threadfence();
        unsigned prev = atomicAdd(&g_count, 1u);
        s_last = (prev == (unsigned)(gridDim.x - 1)) ? 1u : 0u;
    }
    __syncthreads();

    // Last block: sum 1024 partials in a FIXED order (deterministic)
    if (s_last) {
        __threadfence();
        volatile float* gp = g_partial;
        float t0 = (gp[tid]       + gp[tid + 256]) +
                   (gp[tid + 512] + gp[tid + 768]);
        #pragma unroll
        for (int off = 16; off; off >>= 1)
            t0 += __shfl_down_sync(0xFFFFFFFFu, t0, off);
        if ((tid & 31) == 0) s_warp[tid >> 5] = t0;
        __syncthreads();
        if (tid == 0) {
            float tot = 0.0f;
            #pragma unroll
            for (int w = 0; w < 8; w++) tot += s_warp[w];      // fixed order
            out[0]  = tot;
            g_count = 0u;   // reset for next graph replay
        }
    }
}

extern "C" void kernel_launch(void* const* d_in, const int* in_sizes, int n_in,
                              void* d_out, int out_size)
{
    const float* am  = (const float*)d_in[0];  // attention_mask (16,1,256,256) f32
    const float* tgt = (const float*)d_in[1];  // target (2048,6) f32
    (void)in_sizes; (void)n_in; (void)out_size;
    raster_kernel<<<GRID_A, 256>>>(tgt);
    bce_kernel<<<GRID_B, 256>>>(am, (float*)d_out);
}

// round 10
// speedup vs baseline: 1.1662x; 1.1662x over previous
#include <cuda_runtime.h>

// Problem constants (fixed shapes for this problem instance)
#define NBOX   2048
#define NBATCH 16
#define AH     256
#define AW     256
#define GRID   256   // 16 batches x 16 row-bands (16 rows per block)

__device__ float    g_partial[GRID];
__device__ unsigned g_count = 0;

// bce = max(l,0) - l*m + log1p(exp(-|l|)); softplus arg in (1,2] -> fast math safe
__device__ __forceinline__ float bce_elem(float l, unsigned mb) {
    float t  = __expf(-fabsf(l));
    float sp = __logf(1.0f + t);
    float z  = fmaxf(l, 0.0f) - (mb ? l : 0.0f);
    return z + sp;
}

// Counter bump with RELEASE semantics: orders this block's prior global store
// (its partial) at L2 before the increment, WITHOUT a gpu-scope membar/L1 flush.
__device__ __forceinline__ unsigned atom_inc_release(unsigned* p) {
    unsigned prev;
    asm volatile("atom.add.release.gpu.global.u32 %0, [%1], 1;"
                 : "=r"(prev) : "l"(p) : "memory");
    return prev;
}

__global__ __launch_bounds__(256, 8)
void la_loss_kernel(const float* __restrict__ am,
                    const float* __restrict__ tgt,
                    float* __restrict__ out)
{
    const int tid   = threadIdx.x;
    const int blk   = blockIdx.x;
    const int batch = blk >> 4;        // 0..15
    const int rg    = blk & 15;        // band: rows [rg*16, rg*16+16)
    const int blo   = rg << 4;

    // ---- Front-batched prefetch: this block's 4096 logits (16 rows x 256) ----
    const float4* am4  = (const float4*)am;
    const size_t base4 = (size_t)blk * 1024;
    float4 v0 = am4[base4 + tid];
    float4 v1 = am4[base4 + tid + 256];
    float4 v2 = am4[base4 + tid + 512];
    float4 v3 = am4[base4 + tid + 768];

    __shared__ unsigned s_mask[16 * 8];    // 16 rows x 256 bits
    __shared__ float    s_warp[8];
    __shared__ unsigned s_last;

    if (tid < 128) s_mask[tid] = 0u;
    __syncthreads();

    // ---- Phase 1: scan all boxes once, direct-scatter this band's union mask ----
    int has = 0;
    {
        const float fb = (float)batch;
        #pragma unroll
        for (int k = 0; k < NBOX / 256; k++) {
            const float* t = tgt + (size_t)(tid + (k << 8)) * 6;
            if (t[0] == fb) {
                has = 1;
                float xc = t[2], yc = t[3], bw = t[4], bh = t[5];
                float x1 = 1024.0f * (xc - bw * 0.5f);
                float y1 = 1024.0f * (yc - bh * 0.5f);
                float x2 = 1024.0f * (xc + bw * 0.5f);
                float y2 = 1024.0f * (yc + bh * 0.5f);
                bool valid = (x1 <= 1024.0f) && (y1 <= 1024.0f) &&
                             (x2 <= 1024.0f) && (y2 <= 1024.0f);
                int X1 = max(0, (int)truncf(x1 * 0.25f));
                int Y1 = max(0, (int)truncf(y1 * 0.25f));
                int X2 = max(0, min(AW, (int)(ceilf(x2 * 0.25f) + 1.0f)));
                int Y2 = max(0, min(AH, (int)(ceilf(y2 * 0.25f) + 1.0f)));
                int y0  = max(Y1, blo);
                int y1i = min(Y2, blo + 16);
                if (valid && X2 > X1 && y0 < y1i) {
                    int w0 = X1 >> 5;
                    int w1 = (X2 - 1) >> 5;
                    for (int w = w0; w <= w1; w++) {
                        int lo = X1 - (w << 5); lo = (lo < 0) ? 0 : lo;  // 0..31
                        int hi = X2 - (w << 5);                          // >=1
                        unsigned mh  = (hi >= 32) ? 0xFFFFFFFFu : ((1u << hi) - 1u);
                        unsigned msk = mh & ~((1u << lo) - 1u);
                        for (int y = y0; y < y1i; y++)
                            atomicOr(&s_mask[((y - blo) << 3) + w], msk);
                    }
                }
            }
        }
    }
    // Barrier doubles as block-wide has_box OR
    const int anyhas = __syncthreads_or(has);

    // ---- Phase 2: BCE over prefetched logits (16 elems/thread) ----
    float sum = 0.0f;
    {
        #pragma unroll
        for (int j = 0; j < 4; j++) {
            float4 v = (j == 0) ? v0 : (j == 1) ? v1 : (j == 2) ? v2 : v3;
            int p   = tid + (j << 8);            // float4 index within block
            int ty  = p >> 6;                    // 64 float4 per row
            int col = (p & 63) << 2;             // starting bit (mult of 4)
            unsigned bits = s_mask[(ty << 3) + (col >> 5)] >> (col & 31);
            sum += bce_elem(v.x,  bits       & 1u);
            sum += bce_elem(v.y, (bits >> 1) & 1u);
            sum += bce_elem(v.z, (bits >> 2) & 1u);
            sum += bce_elem(v.w, (bits >> 3) & 1u);
        }
    }

    // ---- Phase 3: block reduce (fixed order), publish partial ----
    {
        #pragma unroll
        for (int off = 16; off; off >>= 1)
            sum += __shfl_down_sync(0xFFFFFFFFu, sum, off);
        if ((tid & 31) == 0) s_warp[tid >> 5] = sum;
    }
    __syncthreads();
    if (tid == 0) {
        float tot = 0.0f;
        #pragma unroll
        for (int w = 0; w < 8; w++) tot += s_warp[w];           // fixed order
        g_partial[blk] = anyhas ? tot * (1.0f / 65536.0f) : 0.0f;
        // Release-ordered counter bump: NO gpu membar / L1 flush on this path.
        unsigned prev = atom_inc_release(&g_count);
        s_last = (prev == (unsigned)(gridDim.x - 1)) ? 1u : 0u;
    }
    __syncthreads();

    // ---- Phase 4: last block ONLY sums partials in fixed order ----
    if (s_last) {
        __threadfence();   // one acquire-side fence in one block (not 256)
        float v = *((volatile float*)&g_partial[tid]);   // volatile -> L1-bypass
        #pragma unroll
        for (int off = 16; off; off >>= 1)
            v += __shfl_down_sync(0xFFFFFFFFu, v, off);
        if ((tid & 31) == 0) s_warp[tid >> 5] = v;
        __syncthreads();
        if (tid == 0) {
            float tot = 0.0f;
            #pragma unroll
            for (int w = 0; w < 8; w++) tot += s_warp[w];       // fixed order
            out[0]  = tot;
            g_count = 0u;   // reset for next graph replay
        }
    }
}

extern "C" void kernel_launch(void* const* d_in, const int* in_sizes, int n_in,
                              void* d_out, int out_size)
{
    const float* am  = (const float*)d_in[0];  // attention_mask (16,1,256,256) f32
    const float* tgt = (const float*)d_in[1];  // target (2048,6) f32
    (void)in_sizes; (void)n_in; (void)out_size;
    la_loss_kernel<<<GRID, 256>>>(am, tgt, (float*)d_out);
}

// round 12
// speedup vs baseline: 1.4760x; 1.2657x over previous
#include <cuda_runtime.h>

// Problem constants (fixed shapes for this problem instance)
#define NBOX   2048
#define NBATCH 16
#define AH     256
#define AW     256
#define GRID   512   // 16 batches x 32 bands (8 rows per block)

__device__ float    g_partial[GRID];
__device__ unsigned g_count = 0;

// bce = max(l,0) - l*m + log1p(exp(-|l|)); softplus arg in (1,2] -> fast math safe
__device__ __forceinline__ float bce_elem(float l, unsigned mb) {
    float t  = __expf(-fabsf(l));
    float sp = __logf(1.0f + t);
    float z  = fmaxf(l, 0.0f) - (mb ? l : 0.0f);
    return z + sp;
}

// Release-ordered counter bump: orders this block's prior partial store at L2
// without a gpu-scope membar / L1 flush.
__device__ __forceinline__ unsigned atom_inc_release(unsigned* p) {
    unsigned prev;
    asm volatile("atom.add.release.gpu.global.u32 %0, [%1], 1;"
                 : "=r"(prev) : "l"(p) : "memory");
    return prev;
}

__global__ __launch_bounds__(256, 8)
void la_loss_kernel(const float* __restrict__ am,
                    const float* __restrict__ tgt,
                    float* __restrict__ out)
{
    const int tid   = threadIdx.x;
    const int blk   = blockIdx.x;
    const int batch = blk >> 5;        // 0..15
    const int band  = blk & 31;        // 0..31
    const int blo   = band << 3;       // first row of 8-row band

    // ---- Front-batched prefetch: this block's 2048 logits (8 rows x 256) ----
    const float4* am4  = (const float4*)am;
    const size_t base4 = (size_t)blk * 512;
    float4 v0 = am4[base4 + tid];
    float4 v1 = am4[base4 + tid + 256];

    __shared__ unsigned s_mask[8 * 8];     // 8 rows x 256 bits
    __shared__ float    s_warp[8];
    __shared__ unsigned s_last;

    if (tid < 64) s_mask[tid] = 0u;

    // ---- Phase 0: sampled range-find on sorted bidx (1 load + 2 barrier-counts)
    // samples[j] = bidx[8j]. j0 = #samples < b  =>  first idx >= b in (8(j0-1), 8j0]
    //                        j1 = #samples < b+1 => first idx >= b+1 in (8(j1-1), 8j1]
    // => all batch-b boxes lie in [max(0, 8*j0-7), min(NBOX, 8*j1+1)).
    const float fb  = (float)batch;
    const float fb1 = (float)(batch + 1);
    const float sv  = tgt[(size_t)tid * 48];          // tgt[(tid*8)*6]
    const int j0 = __syncthreads_count(sv < fb);      // barrier also covers s_mask init
    const int j1 = __syncthreads_count(sv < fb1);
    const int lo = max(0, (j0 << 3) - 7);
    const int hi = min(NBOX, (j1 << 3) + 1);

    // ---- Phase 1: scan only the bracketed window; scatter this band's mask ----
    int has = 0;
    for (int i = lo + tid; i < hi; i += 256) {
        const float* t = tgt + (size_t)i * 6;
        if (t[0] == fb) {
            has = 1;
            float xc = t[2], yc = t[3], bw = t[4], bh = t[5];
            float x1 = 1024.0f * (xc - bw * 0.5f);
            float y1 = 1024.0f * (yc - bh * 0.5f);
            float x2 = 1024.0f * (xc + bw * 0.5f);
            float y2 = 1024.0f * (yc + bh * 0.5f);
            bool valid = (x1 <= 1024.0f) && (y1 <= 1024.0f) &&
                         (x2 <= 1024.0f) && (y2 <= 1024.0f);
            int X1 = max(0, (int)truncf(x1 * 0.25f));
            int Y1 = max(0, (int)truncf(y1 * 0.25f));
            int X2 = max(0, min(AW, (int)(ceilf(x2 * 0.25f) + 1.0f)));
            int Y2 = max(0, min(AH, (int)(ceilf(y2 * 0.25f) + 1.0f)));
            int y0  = max(Y1, blo);
            int y1i = min(Y2, blo + 8);
            if (valid && X2 > X1 && y0 < y1i) {
                int w0 = X1 >> 5;
                int w1 = (X2 - 1) >> 5;
                for (int w = w0; w <= w1; w++) {
                    int lob = X1 - (w << 5); lob = (lob < 0) ? 0 : lob;  // 0..31
                    int hib = X2 - (w << 5);                             // >=1
                    unsigned mh  = (hib >= 32) ? 0xFFFFFFFFu : ((1u << hib) - 1u);
                    unsigned msk = mh & ~((1u << lob) - 1u);
                    for (int y = y0; y < y1i; y++)
                        atomicOr(&s_mask[((y - blo) << 3) + w], msk);
                }
            }
        }
    }
    const int anyhas = __syncthreads_or(has);   // barrier + block-wide has_box

    // ---- Phase 2: BCE over prefetched logits (8 elems/thread) ----
    float sum = 0.0f;
    {
        #pragma unroll
        for (int j = 0; j < 2; j++) {
            float4 v = (j == 0) ? v0 : v1;
            int p   = tid + (j << 8);            // float4 index in block (0..511)
            int ty  = p >> 6;                    // row in band (0..7)
            int col = (p & 63) << 2;             // starting bit
            unsigned bits = s_mask[(ty << 3) + (col >> 5)] >> (col & 31);
            sum += bce_elem(v.x,  bits       & 1u);
            sum += bce_elem(v.y, (bits >> 1) & 1u);
            sum += bce_elem(v.z, (bits >> 2) & 1u);
            sum += bce_elem(v.w, (bits >> 3) & 1u);
        }
    }

    // ---- Phase 3: block reduce (fixed order), publish partial ----
    #pragma unroll
    for (int off = 16; off; off >>= 1)
        sum += __shfl_down_sync(0xFFFFFFFFu, sum, off);
    if ((tid & 31) == 0) s_warp[tid >> 5] = sum;
    __syncthreads();
    if (tid == 0) {
        float tot = 0.0f;
        #pragma unroll
        for (int w = 0; w < 8; w++) tot += s_warp[w];          // fixed order
        g_partial[blk] = anyhas ? tot * (1.0f / 65536.0f) : 0.0f;
        unsigned prev = atom_inc_release(&g_count);
        s_last = (prev == (unsigned)(gridDim.x - 1)) ? 1u : 0u;
    }
    __syncthreads();

    // ---- Phase 4: last block sums all partials in fixed order ----
    if (s_last) {
        __threadfence();   // single acquire-side fence, one block only
        volatile float* gp = g_partial;
        float t0 = gp[tid] + gp[tid + 256];
        #pragma unroll
        for (int off = 16; off; off >>= 1)
            t0 += __shfl_down_sync(0xFFFFFFFFu, t0, off);
        if ((tid & 31) == 0) s_warp[tid >> 5] = t0;
        __syncthreads();
        if (tid == 0) {
            float tot = 0.0f;
            #pragma unroll
            for (int w = 0; w < 8; w++) tot += s_warp[w];      // fixed order
            out[0]  = tot;
            g_count = 0u;   // reset for next graph replay
        }
    }
}

extern "C" void kernel_launch(void* const* d_in, const int* in_sizes, int n_in,
                              void* d_out, int out_size)
{
    const float* am  = (const float*)d_in[0];  // attention_mask (16,1,256,256) f32
    const float* tgt = (const float*)d_in[1];  // target (2048,6) f32
    (void)in_sizes; (void)n_in; (void)out_size;
    la_loss_kernel<<<GRID, 256>>>(am, tgt, (float*)d_out);
}